// round 14
// baseline (speedup 1.0000x reference)
#include <cuda_runtime.h>
#include <cuda_fp16.h>
#include <cstdint>

// ============================================================================
// SparseLinear: out[M=8192, N=4096] = X[M,K=4096] @ (W*mask)^T
// sm_103 (no 'a') toolchain => baseline-PTX tensor path:
//   mma.sync.aligned.m16n8k16.row.col.f32.f16.f16.f32
//   ldmatrix.m8n8.x4 + cp.async 4-stage SMEM pipeline.
// Precision lineage (predicted -> measured):
//   R5 bf16 3-prod: 1.5e-5 -> 9.3e-6
//   R7 fp16 2-prod: 2.8e-4 -> 1.85e-4
//   R8 fp16 1-prod: 2.6e-4 -> 2.78e-4   (numerics settled; unchanged here)
// R13 post-mortem: 4 warps/SMSP fixed the latency-hiding deficit (840us).
// Remaining gap vs ~600us issue floor: L2 tile traffic at ~75% of LTS cap
// (4.3GB). This round: CTA tile 128x256 (512 thr, warp 32x64, 4 stages,
// 1 CTA/SM) halves L2 traffic to ~37% cap, keeps 4 warps/SMSP and regs<128.
// ============================================================================

#define DIN   4096
#define DOUT  4096
#define MTOT  8192
#define BM    128
#define BN    256
#define BK    64
#define KCH   (DIN / BK)        // 64 chunks
#define NTILES (DOUT / BN)      // 16
#define MTILES (MTOT / BM)      // 64

// SMEM: X tile 128 rows + W tile 256 rows, 128B data per row padded to 144B
// (conflict-free for ldmatrix and cp.async 16B store phases). 4 stages.
#define PADB    144
#define TILEXB  (128 * PADB)    // 18432
#define TILEWB  (256 * PADB)    // 36864
#define BUFB    (TILEXB + TILEWB)  // 55296
#define STAGES  4
#define SMEMB   (STAGES * BUFB)    // 221184 (< 227KB per-CTA limit)

// ---------------------------------------------------------------------------
// Device-global fp16 scratch (allocation-free rule).
// ---------------------------------------------------------------------------
__device__ __half g_Xh[(size_t)MTOT * DIN];
__device__ __half g_Wh[(size_t)DOUT * DIN];

// ---------------------------------------------------------------------------
// PTX helpers (all baseline sm_80-class instructions — compile at sm_103)
// ---------------------------------------------------------------------------
__device__ __forceinline__ uint32_t smem_to_u32(const void* p) {
    uint32_t a;
    asm("{ .reg .u64 t; cvta.to.shared.u64 t, %1; cvt.u32.u64 %0, t; }"
        : "=r"(a) : "l"(p));
    return a;
}

#define CP_ASYNC16(sa, ga) \
    asm volatile("cp.async.cg.shared.global [%0], [%1], 16;" \
        :: "r"(sa), "l"(ga))

#define CP_COMMIT() asm volatile("cp.async.commit_group;" ::: "memory")
#define CP_WAIT0()  asm volatile("cp.async.wait_group 0;" ::: "memory")
#define CP_WAIT1()  asm volatile("cp.async.wait_group 1;" ::: "memory")
#define CP_WAIT2()  asm volatile("cp.async.wait_group 2;" ::: "memory")
#define CP_WAIT3()  asm volatile("cp.async.wait_group 3;" ::: "memory")

#define LDSM4(r, addr) \
    asm volatile("ldmatrix.sync.aligned.m8n8.x4.shared.b16 {%0,%1,%2,%3}, [%4];" \
        : "=r"((r)[0]), "=r"((r)[1]), "=r"((r)[2]), "=r"((r)[3]) \
        : "r"(addr))

#define MMA16816(d, a, b0, b1) \
    asm volatile( \
        "mma.sync.aligned.m16n8k16.row.col.f32.f16.f16.f32 " \
        "{%0,%1,%2,%3}, {%4,%5,%6,%7}, {%8,%9}, {%0,%1,%2,%3};" \
        : "+f"((d)[0]), "+f"((d)[1]), "+f"((d)[2]), "+f"((d)[3]) \
        : "r"((a)[0]), "r"((a)[1]), "r"((a)[2]), "r"((a)[3]), \
          "r"(b0), "r"(b1))

// ---------------------------------------------------------------------------
// Prep kernels: mask fuse + fp32 -> fp16 round
// ---------------------------------------------------------------------------
__global__ void prep_x_kernel(const float* __restrict__ x) {
    size_t i = ((size_t)blockIdx.x * blockDim.x + threadIdx.x) * 4;
    float4 v = *reinterpret_cast<const float4*>(x + i);
    __half h0 = __float2half_rn(v.x), h1 = __float2half_rn(v.y);
    __half h2 = __float2half_rn(v.z), h3 = __float2half_rn(v.w);
    uint2 hp;
    hp.x = (uint32_t)__half_as_ushort(h0) | ((uint32_t)__half_as_ushort(h1) << 16);
    hp.y = (uint32_t)__half_as_ushort(h2) | ((uint32_t)__half_as_ushort(h3) << 16);
    *reinterpret_cast<uint2*>(g_Xh + i) = hp;
}

__global__ void prep_w_kernel(const float* __restrict__ w,
                              const int* __restrict__ mk) {
    size_t i = ((size_t)blockIdx.x * blockDim.x + threadIdx.x) * 4;
    float4 v = *reinterpret_cast<const float4*>(w + i);
    int4 m = *reinterpret_cast<const int4*>(mk + i);   // int32 mask, 1 per elem
    __half h0 = __float2half_rn(m.x ? v.x : 0.0f);
    __half h1 = __float2half_rn(m.y ? v.y : 0.0f);
    __half h2 = __float2half_rn(m.z ? v.z : 0.0f);
    __half h3 = __float2half_rn(m.w ? v.w : 0.0f);
    uint2 hp;
    hp.x = (uint32_t)__half_as_ushort(h0) | ((uint32_t)__half_as_ushort(h1) << 16);
    hp.y = (uint32_t)__half_as_ushort(h2) | ((uint32_t)__half_as_ushort(h3) << 16);
    *reinterpret_cast<uint2*>(g_Wh + i) = hp;
}

// ---------------------------------------------------------------------------
// GEMM kernel: 128x256 CTA tile, 16 warps (4 M x 4 N), 32x64 warp tile,
// 1 CTA/SM (4 warps/SMSP), 4-stage cp.async pipeline.
// ---------------------------------------------------------------------------
__device__ __forceinline__ void issue_chunk(
    uint32_t smb, int buf, int c, int tid,
    const __half* xh, const __half* wh) {
    // X: 128 rows x 8 segs = 1024 segs; W: 256 rows x 8 segs = 2048 segs.
    // Total 3072 segs / 512 threads = 6 per thread. j<2 -> X, j>=2 -> W.
#pragma unroll
    for (int j = 0; j < 6; j++) {
        int seg = tid & 7;
        if (j < 2) {
            int row = j * 64 + (tid >> 3);
            const __half* gp = xh + (size_t)row * DIN + c * BK + seg * 8;
            uint32_t sa = smb + buf * BUFB + row * PADB + seg * 16;
            CP_ASYNC16(sa, gp);
        } else {
            int row = (j - 2) * 64 + (tid >> 3);
            const __half* gp = wh + (size_t)row * DIN + c * BK + seg * 8;
            uint32_t sa = smb + buf * BUFB + TILEXB + row * PADB + seg * 16;
            CP_ASYNC16(sa, gp);
        }
    }
    CP_COMMIT();
}

__global__ __launch_bounds__(512, 1)
void sparse_linear_hmma_kernel(float* __restrict__ out) {
    extern __shared__ __align__(16) char sm[];
    uint32_t smb = smem_to_u32(sm);
    const int tid  = threadIdx.x;
    const int wid  = tid >> 5;
    const int lane = tid & 31;
    const int wm = (wid >> 2) * 32;   // warp M offset (0,32,64,96)
    const int wn = (wid & 3) * 64;    // warp N offset (0,64,128,192)

    const size_t mbase = (size_t)blockIdx.y * BM;
    const size_t nbase = (size_t)blockIdx.x * BN;

    const __half* xh = g_Xh + mbase * DIN;
    const __half* wh = g_Wh + nbase * DIN;

    float acc[2][8][4];
#pragma unroll
    for (int mi = 0; mi < 2; mi++)
#pragma unroll
        for (int ni = 0; ni < 8; ni++)
#pragma unroll
            for (int q = 0; q < 4; q++) acc[mi][ni][q] = 0.0f;

    // ldmatrix lane addressing (144B padded rows -> conflict-free):
    const int arow_l = lane & 15;
    const int akb_l  = (lane >> 4) << 4;
    const int brow_l = (lane & 7) + ((lane >> 4) << 3);
    const int bkb_l  = ((lane >> 3) & 1) << 4;

    // Prologue: stages 0..3.
    issue_chunk(smb, 0, 0, tid, xh, wh);
    issue_chunk(smb, 1, 1, tid, xh, wh);
    issue_chunk(smb, 2, 2, tid, xh, wh);
    issue_chunk(smb, 3, 3, tid, xh, wh);

    int buf = 0;
#pragma unroll 1
    for (int c = 0; c < KCH; c++) {
        // Chunks issued so far = min(c+4, KCH). Need chunk c complete:
        if (c <= KCH - 4)      CP_WAIT3();
        else if (c == KCH - 3) CP_WAIT2();
        else if (c == KCH - 2) CP_WAIT1();
        else                   CP_WAIT0();
        __syncthreads();

        const uint32_t tb = smb + buf * BUFB;
#pragma unroll
        for (int ks = 0; ks < 4; ks++) {
            uint32_t Ah[8], Bh[16];
            const int akb = ks * 32 + akb_l;
            const int bkb = ks * 32 + bkb_l;
#pragma unroll
            for (int mi = 0; mi < 2; mi++) {
                uint32_t ra = tb + (wm + mi * 16 + arow_l) * PADB + akb;
                LDSM4(&Ah[mi * 4], ra);
            }
#pragma unroll
            for (int g = 0; g < 4; g++) {
                uint32_t rb = tb + TILEXB + (wn + g * 16 + brow_l) * PADB + bkb;
                LDSM4(&Bh[g * 4], rb);
            }
#pragma unroll
            for (int mi = 0; mi < 2; mi++)
#pragma unroll
                for (int ni = 0; ni < 8; ni++) {
                    const int g = ni >> 1, pr = ni & 1;
                    MMA16816(acc[mi][ni], &Ah[mi * 4],
                             Bh[g * 4 + pr * 2], Bh[g * 4 + pr * 2 + 1]);
                }
        }
        __syncthreads();

        if (c + 4 < KCH) issue_chunk(smb, buf, c + 4, tid, xh, wh);
        buf = (buf == STAGES - 1) ? 0 : buf + 1;
    }

    // Epilogue: c-frag layout -> direct float2 stores.
    const int r0 = lane >> 2;
    const int cc = 2 * (lane & 3);
#pragma unroll
    for (int mi = 0; mi < 2; mi++) {
#pragma unroll
        for (int ni = 0; ni < 8; ni++) {
            size_t row = mbase + wm + mi * 16 + r0;
            size_t col = nbase + wn + ni * 8 + cc;
            float2 v0 = make_float2(acc[mi][ni][0], acc[mi][ni][1]);
            float2 v1 = make_float2(acc[mi][ni][2], acc[mi][ni][3]);
            *reinterpret_cast<float2*>(out + row * DOUT + col) = v0;
            *reinterpret_cast<float2*>(out + (row + 8) * DOUT + col) = v1;
        }
    }
}

// ---------------------------------------------------------------------------
// Launch
// ---------------------------------------------------------------------------
extern "C" void kernel_launch(void* const* d_in, const int* in_sizes, int n_in,
                              void* d_out, int out_size) {
    const float* x  = (const float*)d_in[0];
    const float* w  = (const float*)d_in[1];
    const int*   mk = (const int*)d_in[2];     // bool upcast to int32 by harness
    float* out = (float*)d_out;

    prep_x_kernel<<<((size_t)MTOT * DIN) / 4 / 256, 256>>>(x);
    prep_w_kernel<<<((size_t)DOUT * DIN) / 4 / 256, 256>>>(w, mk);

    cudaFuncSetAttribute(sparse_linear_hmma_kernel,
                         cudaFuncAttributeMaxDynamicSharedMemorySize, SMEMB);
    sparse_linear_hmma_kernel<<<dim3(NTILES, MTILES), 512, SMEMB>>>(out);
}

// round 17
// speedup vs baseline: 1.0987x; 1.0987x over previous
#include <cuda_runtime.h>
#include <cuda_fp16.h>
#include <cstdint>

// ============================================================================
// SparseLinear: out[M=8192, N=4096] = X[M,K=4096] @ (W*mask)^T
// sm_103 (no 'a') toolchain => baseline-PTX tensor path:
//   mma.sync.aligned.m16n8k16.row.col.f32.f16.f16.f32
//   ldmatrix.m8n8.x4 + cp.async 3-stage SMEM pipeline, 2 CTAs/SM.
// Precision lineage (predicted -> measured):
//   R5 bf16 3-prod: 1.5e-5 -> 9.3e-6
//   R7 fp16 2-prod: 2.8e-4 -> 1.85e-4
//   R8 fp16 1-prod: 2.6e-4 -> 2.78e-4   (numerics settled; unchanged here)
// R13 (2 CTAs/SM, 2 barriers/chunk) = 840us. R14 (128x256) = 879us =>
// L2 not binding; cross-CTA overlap at barriers is load-bearing.
// R15 (this kernel): single __syncthreads per chunk + issue-before-compute.
// R15 bench was an infra failure (same broker error as R1 on the stub);
// pipeline re-audited for deadlock (wait-group invariant: pending <= {G(c),
// G(c+1)} at top of iter c; WAIT1 => G(c) complete). Resubmitting unchanged.
// ============================================================================

#define DIN   4096
#define DOUT  4096
#define MTOT  8192
#define BM    128
#define BN    128
#define BK    64
#define KCH   (DIN / BK)        // 64 chunks
#define NTILES (DOUT / BN)      // 32
#define MTILES (MTOT / BM)      // 64

// SMEM: 2 tiles (Xh, Wh) per stage, 128 rows x 128B data, rows padded to
// 144B (conflict-free for ldmatrix and cp.async 16B store phases). 3 stages.
#define PADB   144
#define TILEB  (128 * PADB)     // 18432
#define BUFB   (2 * TILEB)      // 36864
#define STAGES 3
#define SMEMB  (STAGES * BUFB)  // 110592  (x2 CTAs = 221184 < 228KB SM limit)

// ---------------------------------------------------------------------------
// Device-global fp16 scratch (allocation-free rule).
// ---------------------------------------------------------------------------
__device__ __half g_Xh[(size_t)MTOT * DIN];
__device__ __half g_Wh[(size_t)DOUT * DIN];

// ---------------------------------------------------------------------------
// PTX helpers (all baseline sm_80-class instructions — compile at sm_103)
// ---------------------------------------------------------------------------
__device__ __forceinline__ uint32_t smem_to_u32(const void* p) {
    uint32_t a;
    asm("{ .reg .u64 t; cvta.to.shared.u64 t, %1; cvt.u32.u64 %0, t; }"
        : "=r"(a) : "l"(p));
    return a;
}

#define CP_ASYNC16(sa, ga) \
    asm volatile("cp.async.cg.shared.global [%0], [%1], 16;" \
        :: "r"(sa), "l"(ga))

#define CP_COMMIT() asm volatile("cp.async.commit_group;" ::: "memory")
#define CP_WAIT0()  asm volatile("cp.async.wait_group 0;" ::: "memory")
#define CP_WAIT1()  asm volatile("cp.async.wait_group 1;" ::: "memory")

#define LDSM4(r, addr) \
    asm volatile("ldmatrix.sync.aligned.m8n8.x4.shared.b16 {%0,%1,%2,%3}, [%4];" \
        : "=r"((r)[0]), "=r"((r)[1]), "=r"((r)[2]), "=r"((r)[3]) \
        : "r"(addr))

#define MMA16816(d, a, b0, b1) \
    asm volatile( \
        "mma.sync.aligned.m16n8k16.row.col.f32.f16.f16.f32 " \
        "{%0,%1,%2,%3}, {%4,%5,%6,%7}, {%8,%9}, {%0,%1,%2,%3};" \
        : "+f"((d)[0]), "+f"((d)[1]), "+f"((d)[2]), "+f"((d)[3]) \
        : "r"((a)[0]), "r"((a)[1]), "r"((a)[2]), "r"((a)[3]), \
          "r"(b0), "r"(b1))

// ---------------------------------------------------------------------------
// Prep kernels: mask fuse + fp32 -> fp16 round
// ---------------------------------------------------------------------------
__global__ void prep_x_kernel(const float* __restrict__ x) {
    size_t i = ((size_t)blockIdx.x * blockDim.x + threadIdx.x) * 4;
    float4 v = *reinterpret_cast<const float4*>(x + i);
    __half h0 = __float2half_rn(v.x), h1 = __float2half_rn(v.y);
    __half h2 = __float2half_rn(v.z), h3 = __float2half_rn(v.w);
    uint2 hp;
    hp.x = (uint32_t)__half_as_ushort(h0) | ((uint32_t)__half_as_ushort(h1) << 16);
    hp.y = (uint32_t)__half_as_ushort(h2) | ((uint32_t)__half_as_ushort(h3) << 16);
    *reinterpret_cast<uint2*>(g_Xh + i) = hp;
}

__global__ void prep_w_kernel(const float* __restrict__ w,
                              const int* __restrict__ mk) {
    size_t i = ((size_t)blockIdx.x * blockDim.x + threadIdx.x) * 4;
    float4 v = *reinterpret_cast<const float4*>(w + i);
    int4 m = *reinterpret_cast<const int4*>(mk + i);   // int32 mask, 1 per elem
    __half h0 = __float2half_rn(m.x ? v.x : 0.0f);
    __half h1 = __float2half_rn(m.y ? v.y : 0.0f);
    __half h2 = __float2half_rn(m.z ? v.z : 0.0f);
    __half h3 = __float2half_rn(m.w ? v.w : 0.0f);
    uint2 hp;
    hp.x = (uint32_t)__half_as_ushort(h0) | ((uint32_t)__half_as_ushort(h1) << 16);
    hp.y = (uint32_t)__half_as_ushort(h2) | ((uint32_t)__half_as_ushort(h3) << 16);
    *reinterpret_cast<uint2*>(g_Wh + i) = hp;
}

// ---------------------------------------------------------------------------
// GEMM kernel: 128x128 CTA tile, 8 warps (2 M x 4 N), 64x32 warp tile,
// 2 CTAs per SM, single barrier per chunk (issue-before-compute).
// ---------------------------------------------------------------------------
__device__ __forceinline__ void issue_chunk(
    uint32_t smb, int buf, int c, int tid,
    const __half* xh, const __half* wh) {
    // 2 tiles x 128 rows x 8 segs(16B) = 2048 segs / 256 thr = 8 per thread.
#pragma unroll
    for (int j = 0; j < 8; j++) {
        const int tile = j >> 2;                   // compile-time 0..1
        int row = 32 * (j & 3) + (tid >> 3);
        int seg = tid & 7;
        const __half* gp = (tile ? wh : xh) + (size_t)row * DIN + c * BK + seg * 8;
        uint32_t sa = smb + buf * BUFB + tile * TILEB + row * PADB + seg * 16;
        CP_ASYNC16(sa, gp);
    }
    CP_COMMIT();
}

__global__ __launch_bounds__(256, 2)
void sparse_linear_hmma_kernel(float* __restrict__ out) {
    extern __shared__ __align__(16) char sm[];
    uint32_t smb = smem_to_u32(sm);
    const int tid  = threadIdx.x;
    const int wid  = tid >> 5;
    const int lane = tid & 31;
    const int wm = (wid >> 2) * 64;   // warp M offset within CTA (0 or 64)
    const int wn = (wid & 3) * 32;    // warp N offset within CTA (0..96)

    const size_t mbase = (size_t)blockIdx.y * BM;
    const size_t nbase = (size_t)blockIdx.x * BN;

    const __half* xh = g_Xh + mbase * DIN;
    const __half* wh = g_Wh + nbase * DIN;

    float acc[4][4][4];
#pragma unroll
    for (int mi = 0; mi < 4; mi++)
#pragma unroll
        for (int ni = 0; ni < 4; ni++)
#pragma unroll
            for (int q = 0; q < 4; q++) acc[mi][ni][q] = 0.0f;

    // ldmatrix lane addressing (144B padded rows -> conflict-free):
    const int arow_l = lane & 15;
    const int akb_l  = (lane >> 4) << 4;
    const int brow_l = (lane & 7) + ((lane >> 4) << 3);
    const int bkb_l  = ((lane >> 3) & 1) << 4;

    // Prologue: chunks 0,1 into buffers 0,1. Chunk 2 is issued inside iter 0.
    issue_chunk(smb, 0, 0, tid, xh, wh);
    issue_chunk(smb, 1, 1, tid, xh, wh);

    int buf = 0;        // buffer of chunk c
    int nbuf = 2;       // buffer receiving chunk c+2 (= buffer of chunk c-1)
#pragma unroll 1
    for (int c = 0; c < KCH; c++) {
        // Invariant at top of iter c: pending groups <= {G(c), G(c+1)}.
        // wait_group 1 => at most one pending => G(c) complete.
        if (c < KCH - 1) CP_WAIT1();
        else             CP_WAIT0();
        __syncthreads();
        // After the sync: every thread finished compute(c-1) before its wait
        // above, so buf(c-1) == nbuf is globally free. Start its refill NOW,
        // a full compute-phase earlier than the old 2-barrier scheme.
        if (c + 2 < KCH) issue_chunk(smb, nbuf, c + 2, tid, xh, wh);

        const uint32_t tb = smb + buf * BUFB;
#pragma unroll
        for (int ks = 0; ks < 4; ks++) {
            uint32_t Ah[16], Bh[8];
            const int akb = ks * 32 + akb_l;
            const int bkb = ks * 32 + bkb_l;
#pragma unroll
            for (int mi = 0; mi < 4; mi++) {
                uint32_t ra = tb + (wm + mi * 16 + arow_l) * PADB + akb;
                LDSM4(&Ah[mi * 4], ra);
            }
#pragma unroll
            for (int g = 0; g < 2; g++) {
                uint32_t rb = tb + TILEB + (wn + g * 16 + brow_l) * PADB + bkb;
                LDSM4(&Bh[g * 4], rb);
            }
#pragma unroll
            for (int mi = 0; mi < 4; mi++)
#pragma unroll
                for (int ni = 0; ni < 4; ni++)
                    MMA16816(acc[mi][ni], &Ah[mi * 4], Bh[ni * 2], Bh[ni * 2 + 1]);
        }

        nbuf = buf;
        buf = (buf == STAGES - 1) ? 0 : buf + 1;
    }

    // Epilogue: c-frag layout -> direct float2 stores.
    const int r0 = lane >> 2;
    const int cc = 2 * (lane & 3);
#pragma unroll
    for (int mi = 0; mi < 4; mi++) {
#pragma unroll
        for (int ni = 0; ni < 4; ni++) {
            size_t row = mbase + wm + mi * 16 + r0;
            size_t col = nbase + wn + ni * 8 + cc;
            float2 v0 = make_float2(acc[mi][ni][0], acc[mi][ni][1]);
            float2 v1 = make_float2(acc[mi][ni][2], acc[mi][ni][3]);
            *reinterpret_cast<float2*>(out + row * DOUT + col) = v0;
            *reinterpret_cast<float2*>(out + (row + 8) * DOUT + col) = v1;
        }
    }
}

// ---------------------------------------------------------------------------
// Launch
// ---------------------------------------------------------------------------
extern "C" void kernel_launch(void* const* d_in, const int* in_sizes, int n_in,
                              void* d_out, int out_size) {
    const float* x  = (const float*)d_in[0];
    const float* w  = (const float*)d_in[1];
    const int*   mk = (const int*)d_in[2];     // bool upcast to int32 by harness
    float* out = (float*)d_out;

    prep_x_kernel<<<((size_t)MTOT * DIN) / 4 / 256, 256>>>(x);
    prep_w_kernel<<<((size_t)DOUT * DIN) / 4 / 256, 256>>>(w, mk);

    cudaFuncSetAttribute(sparse_linear_hmma_kernel,
                         cudaFuncAttributeMaxDynamicSharedMemorySize, SMEMB);
    sparse_linear_hmma_kernel<<<dim3(NTILES, MTILES), 256, SMEMB>>>(out);
}